// round 2
// baseline (speedup 1.0000x reference)
#include <cuda_runtime.h>
#include <math.h>

// Problem dims (fixed)
#define S_ 256
#define B_ 256
#define I_ 256
#define H_ 512
#define G_ 2048            // 4*H
#define SB_ (S_*B_)        // 65536
#define BH_ (B_*H_)        // 131072
#define LBH_ (2*BH_)       // 262144
#define OUT_OFF_H (SB_*H_) // 33554432
#define OUT_OFF_C (OUT_OFF_H + LBH_)

// Scratch (device globals: no allocation allowed)
__device__ float g_X[(size_t)SB_ * G_];   // 512 MB: X0, then reused for X1
__device__ float g_H0[(size_t)SB_ * H_];  // 128 MB: unmasked layer-0 h outputs
__device__ float g_hstate[2][LBH_];       // ping-pong h state, [parity][layer*BH + ...]
__device__ float g_cstate[LBH_];          // c state (owner-exclusive, in-place)

__device__ __forceinline__ float sig_(float x) { return 1.0f / (1.0f + __expf(-x)); }
__device__ __forceinline__ float tanh_(float x) { return 2.0f / (1.0f + __expf(-2.0f*x)) - 1.0f; }

// ---------------------------------------------------------------------------
// Big batched GEMM: C[m,n] = sum_k A[m,k]*W[n,k] + b1[n] + b2[n]
// M = 65536 (=S*B), N = 2048, K = 256 or 512. C = g_X.
// Tiles: 128x128x8, 256 threads, 8x8 microtile.
// ---------------------------------------------------------------------------
__global__ void __launch_bounds__(256) gemm_bias_kernel(
    const float* __restrict__ Aext, int use_gH0,
    const float* __restrict__ W,
    const float* __restrict__ b1, const float* __restrict__ b2,
    int K)
{
    __shared__ float As[8][128];
    __shared__ float Ws[8][132];

    const float* __restrict__ A = use_gH0 ? g_H0 : Aext;

    const int bn = blockIdx.x;        // 0..15   (N tiles)
    const int bm = blockIdx.y;        // 0..511  (M tiles)
    const int tid = threadIdx.x;
    const int row = tid >> 1;         // 0..127
    const int kq  = (tid & 1) << 2;   // 0 or 4
    const int ty  = tid >> 4;         // 0..15
    const int tx  = tid & 15;         // 0..15

    float acc[8][8];
    #pragma unroll
    for (int i = 0; i < 8; i++)
        #pragma unroll
        for (int j = 0; j < 8; j++) acc[i][j] = 0.0f;

    const float* Ap = A + (size_t)(bm*128 + row)*K + kq;
    const float* Wp = W + (size_t)(bn*128 + row)*K + kq;

    for (int k0 = 0; k0 < K; k0 += 8) {
        float4 a = *(const float4*)(Ap + k0);
        float4 w = *(const float4*)(Wp + k0);
        __syncthreads();
        As[kq+0][row] = a.x; As[kq+1][row] = a.y; As[kq+2][row] = a.z; As[kq+3][row] = a.w;
        Ws[kq+0][row] = w.x; Ws[kq+1][row] = w.y; Ws[kq+2][row] = w.z; Ws[kq+3][row] = w.w;
        __syncthreads();
        #pragma unroll
        for (int k = 0; k < 8; k++) {
            float af[8], wf[8];
            *(float4*)(af)   = *(const float4*)&As[k][ty*8];
            *(float4*)(af+4) = *(const float4*)&As[k][ty*8+4];
            *(float4*)(wf)   = *(const float4*)&Ws[k][tx*8];
            *(float4*)(wf+4) = *(const float4*)&Ws[k][tx*8+4];
            #pragma unroll
            for (int i = 0; i < 8; i++)
                #pragma unroll
                for (int j = 0; j < 8; j++)
                    acc[i][j] = fmaf(af[i], wf[j], acc[i][j]);
        }
    }

    #pragma unroll
    for (int j = 0; j < 8; j++) {
        const int n = bn*128 + tx*8 + j;
        const float bias = b1[n] + b2[n];
        #pragma unroll
        for (int i = 0; i < 8; i++) {
            const int m = bm*128 + ty*8 + i;
            g_X[(size_t)m*G_ + n] = acc[i][j] + bias;
        }
    }
}

// ---------------------------------------------------------------------------
// Fused per-step kernel: gates = Xpre + h@W_hh^T, then LSTM cell + masking.
// Block: 32 batch rows x 32 h-cols (=> 128 GEMM cols: 4 gates per h-col).
// Grid: (H/32=16, B/32=8) = 128 blocks, 256 threads.
// Microtile: 4 rows x 4 gate-cols (one h-col, gates i,f,g,o).
// ---------------------------------------------------------------------------
__global__ void __launch_bounds__(256) lstm_step_kernel(
    int t, int layer,
    const float* __restrict__ W,      // W_hh: (2048, 512)
    const float* __restrict__ done,   // (S, B)
    float* __restrict__ out)          // d_out base (used for layer 1)
{
    __shared__ float As[16][32];      // [k][batch row]
    __shared__ float Ws[16][132];     // [k][lc], lc = local_hcol*4 + gate

    const float* __restrict__ Xpre = g_X + (size_t)t * B_ * G_;
    const int p = t & 1;
    const float* __restrict__ hin  = g_hstate[p]     + layer*BH_;
    float* __restrict__ hout       = g_hstate[p ^ 1] + layer*BH_;
    float* __restrict__ cst        = g_cstate        + layer*BH_;
    float* __restrict__ hum        = (layer == 0) ? (g_H0 + (size_t)t*BH_)
                                                  : (out  + (size_t)t*BH_);
    const float* __restrict__ done_row = done + t*B_;

    const int bn = blockIdx.x;        // h-col tile 0..15
    const int bm = blockIdx.y;        // batch tile 0..7
    const int tid = threadIdx.x;
    const int rg = tid >> 5;          // 0..7  (row group of 4)
    const int cg = tid & 31;          // 0..31 (h-col within tile)

    const int arow = tid >> 2;        // for A loads (tid < 128): 0..31
    const int akq  = (tid & 3) << 2;

    float acc[4][4];
    #pragma unroll
    for (int i = 0; i < 4; i++)
        #pragma unroll
        for (int j = 0; j < 4; j++) acc[i][j] = 0.0f;

    for (int k0 = 0; k0 < H_; k0 += 16) {
        float4 av = make_float4(0.f,0.f,0.f,0.f);
        if (tid < 128)
            av = *(const float4*)&hin[(bm*32 + arow)*H_ + k0 + akq];

        // W tile: 128 lc-rows x 16 k = 512 float4 loads -> 2 per thread
        float4 wv0, wv1;
        {
            int idx = tid*2;
            int lc = idx >> 2, kq2 = (idx & 3) << 2;
            int j  = (lc & 3)*H_ + bn*32 + (lc >> 2);     // W_hh row: gate*512 + hcol
            wv0 = *(const float4*)&W[(size_t)j*H_ + k0 + kq2];
            idx = tid*2 + 1;
            lc = idx >> 2; kq2 = (idx & 3) << 2;
            j  = (lc & 3)*H_ + bn*32 + (lc >> 2);
            wv1 = *(const float4*)&W[(size_t)j*H_ + k0 + kq2];
        }

        __syncthreads();
        if (tid < 128) {
            As[akq+0][arow] = av.x; As[akq+1][arow] = av.y;
            As[akq+2][arow] = av.z; As[akq+3][arow] = av.w;
        }
        {
            int idx = tid*2;
            int lc = idx >> 2, kq2 = (idx & 3) << 2;
            Ws[kq2+0][lc] = wv0.x; Ws[kq2+1][lc] = wv0.y;
            Ws[kq2+2][lc] = wv0.z; Ws[kq2+3][lc] = wv0.w;
            idx = tid*2 + 1; lc = idx >> 2; kq2 = (idx & 3) << 2;
            Ws[kq2+0][lc] = wv1.x; Ws[kq2+1][lc] = wv1.y;
            Ws[kq2+2][lc] = wv1.z; Ws[kq2+3][lc] = wv1.w;
        }
        __syncthreads();

        #pragma unroll
        for (int k = 0; k < 16; k++) {
            float a[4], b4[4];
            *(float4*)a  = *(const float4*)&As[k][rg*4];   // broadcast within warp
            *(float4*)b4 = *(const float4*)&Ws[k][cg*4];   // 4 gates of one h-col
            #pragma unroll
            for (int i = 0; i < 4; i++)
                #pragma unroll
                for (int j = 0; j < 4; j++)
                    acc[i][j] = fmaf(a[i], b4[j], acc[i][j]);
        }
    }

    const int jcol = bn*32 + cg;      // global h-col
    #pragma unroll
    for (int i = 0; i < 4; i++) {
        const int b = bm*32 + rg*4 + i;
        const float gi = acc[i][0] + Xpre[b*G_           + jcol];
        const float gf = acc[i][1] + Xpre[b*G_ +   H_    + jcol];
        const float gg = acc[i][2] + Xpre[b*G_ + 2*H_    + jcol];
        const float go = acc[i][3] + Xpre[b*G_ + 3*H_    + jcol];
        const float co = cst[b*H_ + jcol];
        const float iv = sig_(gi);
        const float fv = sig_(gf);
        const float gv = tanh_(gg);
        const float ov = sig_(go);
        const float cn = fv*co + iv*gv;
        const float hn = ov * tanh_(cn);
        const float m  = 1.0f - done_row[b];
        hum[b*H_ + jcol]  = hn;        // unmasked (layer-1 input / outputs)
        hout[b*H_ + jcol] = hn * m;    // carried state (masked)
        cst[b*H_ + jcol]  = cn * m;
    }
}

// ---------------------------------------------------------------------------
__global__ void init_states_kernel(const float* __restrict__ h0,
                                   const float* __restrict__ c0)
{
    int i = blockIdx.x*blockDim.x + threadIdx.x;
    if (i < LBH_) {
        g_hstate[0][i] = h0[i];
        g_hstate[1][i] = 0.0f;
        g_cstate[i]    = c0[i];
    }
}

__global__ void finalize_kernel(float* __restrict__ out)
{
    int i = blockIdx.x*blockDim.x + threadIdx.x;
    if (i < LBH_) {
        out[OUT_OFF_H + i] = g_hstate[0][i];  // after 256 steps, final parity = 0
        out[OUT_OFF_C + i] = g_cstate[i];
    }
}

// ---------------------------------------------------------------------------
extern "C" void kernel_launch(void* const* d_in, const int* in_sizes, int n_in,
                              void* d_out, int out_size)
{
    const float* x    = (const float*)d_in[0];
    const float* h0   = (const float*)d_in[1];
    const float* c0   = (const float*)d_in[2];
    const float* done = (const float*)d_in[3];
    const float* Wih0 = (const float*)d_in[4];
    const float* Whh0 = (const float*)d_in[5];
    const float* bih0 = (const float*)d_in[6];
    const float* bhh0 = (const float*)d_in[7];
    const float* Wih1 = (const float*)d_in[8];
    const float* Whh1 = (const float*)d_in[9];
    const float* bih1 = (const float*)d_in[10];
    const float* bhh1 = (const float*)d_in[11];
    float* out = (float*)d_out;

    init_states_kernel<<<(LBH_ + 255)/256, 256>>>(h0, c0);

    dim3 ggrid(G_/128, SB_/128);   // (16, 512)
    dim3 sgrid(H_/32, B_/32);      // (16, 8)

    // Pass 1: layer 0
    gemm_bias_kernel<<<ggrid, 256>>>(x, 0, Wih0, bih0, bhh0, I_);
    for (int t = 0; t < S_; t++)
        lstm_step_kernel<<<sgrid, 256>>>(t, 0, Whh0, done, out);

    // Pass 2: layer 1 (input = unmasked layer-0 outputs)
    gemm_bias_kernel<<<ggrid, 256>>>(nullptr, 1, Wih1, bih1, bhh1, H_);
    for (int t = 0; t < S_; t++)
        lstm_step_kernel<<<sgrid, 256>>>(t, 1, Whh1, done, out);

    finalize_kernel<<<(LBH_ + 255)/256, 256>>>(out);
}